// round 3
// baseline (speedup 1.0000x reference)
#include <cuda_runtime.h>
#include <math.h>

// Problem dims
#define Ln  8
#define Tn  512
#define Hn  128
#define Bn  64
#define G4  512     // 4*H
#define Vn  65
#define On  65

#define NC   32     // gate columns per CTA
#define CPL  16     // CTAs per layer
#define NTHR 256

#define OUT_MAIN   (Bn*Tn*On)          // outputs [B][T][OUT]
#define OUT_H_BASE (OUT_MAIN)          // hT [L][B][H]
#define OUT_C_BASE (OUT_MAIN + Ln*Bn*Hn)

// Scratch (allocation-free rule: __device__ globals)
__device__ float    g_hseq[Ln*Tn*Hn*Bn];   // [l][t][u][b]  128 MB
__device__ float    g_tok[Vn*G4];          // embed@w_ih[0] + b_ih0 + b_hh0
__device__ int      g_xT[Tn*Bn];           // tokens transposed [t][b]
__device__ unsigned g_cnt[Ln*Tn];          // completion counters

__device__ __forceinline__ unsigned ld_acq(const unsigned* p){
    unsigned v;
    asm volatile("ld.acquire.gpu.global.u32 %0, [%1];" : "=r"(v) : "l"(p) : "memory");
    return v;
}
__device__ __forceinline__ void red_rel_add(unsigned* p){
    asm volatile("red.release.gpu.global.add.u32 [%0], 1;" :: "l"(p) : "memory");
}
__device__ __forceinline__ float sigm(float x){ return 1.f/(1.f + __expf(-x)); }

// ---------------------------------------------------------------------------
// Reset flags + transpose tokens
__global__ void k_reset(const int* __restrict__ x){
    int i = blockIdx.x*blockDim.x + threadIdx.x;
    if (i < Ln*Tn) g_cnt[i] = 0u;
    if (i < Tn*Bn){
        int t = i / Bn, b = i % Bn;
        g_xT[i] = x[b*Tn + t];
    }
}

// ---------------------------------------------------------------------------
// Token gate table for layer 0: g_tok[v][c] = sum_k embed[v][k]*w_ih0[k][c] + b_ih0[c] + b_hh0[c]
__global__ void k_token(const float* __restrict__ embed, const float* __restrict__ w_ih,
                        const float* __restrict__ b_ih, const float* __restrict__ b_hh){
    __shared__ float e[Hn];
    int v = blockIdx.x, c = threadIdx.x;
    if (c < Hn) e[c] = embed[v*Hn + c];
    __syncthreads();
    float acc = b_ih[c] + b_hh[c];
#pragma unroll 8
    for (int k = 0; k < Hn; ++k) acc += e[k] * w_ih[k*G4 + c];
    g_tok[v*G4 + c] = acc;
}

// ---------------------------------------------------------------------------
// Persistent wavefront LSTM: 8 layers x 16 CTAs, all co-resident.
__global__ void __launch_bounds__(NTHR, 1) k_lstm(
    const float* __restrict__ w_ih, const float* __restrict__ b_ih,
    const float* __restrict__ w_hh, const float* __restrict__ b_hh,
    float* __restrict__ out)
{
    extern __shared__ float sm[];
    float* Wsm = sm;               // [256][32]  combined [w_ih; w_hh] column slice
    float* Z   = sm + 8192;        // [256][64]  combined [inp; h_prev], b-contiguous
    float* Gsm = Z + 16384;        // [32][64]   gate preactivations
    float* Bsm = Gsm + 2048;       // [32]       folded biases (layers >= 1)

    const int layer = blockIdx.x >> 4;
    const int gidx  = blockIdx.x & 15;     // unit group: units [8*gidx, 8*gidx+8)
    const int tid   = threadIdx.x;

    // Stage weight slice into SMEM. local col cl: gate = cl>>3, ul = cl&7
    for (int i = tid; i < 256*NC; i += NTHR){
        int k  = i >> 5, cl = i & 31;
        int col = ((cl >> 3) << 7) + (gidx << 3) + (cl & 7);
        float w = (k < Hn) ? w_ih[(layer*Hn + k)*G4 + col]
                           : w_hh[(layer*Hn + (k-Hn))*G4 + col];
        Wsm[k*NC + cl] = w;
    }
    if (tid < NC){
        int col = ((tid >> 3) << 7) + (gidx << 3) + (tid & 7);
        Bsm[tid] = b_ih[layer*G4 + col] + b_hh[layer*G4 + col];
    }
    __syncthreads();

    // Compute microtile: 2 local cols x 4 batch per thread
    const int c0  = (tid >> 4) * 2;        // local col, even
    const int b0  = (tid & 15) * 4;
    const int gc0 = ((c0 >> 3) << 7) + (gidx << 3) + (c0 & 7);
    const int gc1 = gc0 + 1;               // c0 even -> same gate

    // Elementwise mapping: 2 (unit,b) pairs per thread
    const int p0   = tid * 2;
    const int e_ul = p0 >> 6;              // 0..7
    const int e_b  = p0 & 63;              // even
    const int e_u  = (gidx << 3) + e_ul;

    float cst0 = 0.f, cst1 = 0.f;

    unsigned* cnt_own   = &g_cnt[layer*Tn];
    unsigned* cnt_below = (layer > 0) ? &g_cnt[(layer-1)*Tn] : nullptr;

    for (int t = 0; t < Tn; ++t){
        // ---- wait for dependencies ----
        if (tid == 0){
            if (layer > 0){ while (ld_acq(&cnt_below[t])   < CPL) __nanosleep(32); }
            if (t > 0)    { while (ld_acq(&cnt_own[t-1])   < CPL) __nanosleep(32); }
        }
        __syncthreads();

        // ---- load Z = [inp(128x64) ; h_prev(128x64)] ----
        if (layer > 0){
            const float4* s = (const float4*)&g_hseq[((layer-1)*Tn + t)*Hn*Bn];
            float4* d = (float4*)Z;
            for (int i = tid; i < 2048; i += NTHR) d[i] = s[i];
        }
        if (t > 0){
            const float4* s = (const float4*)&g_hseq[(layer*Tn + (t-1))*Hn*Bn];
            float4* d = (float4*)(Z + Hn*Bn);
            for (int i = tid; i < 2048; i += NTHR) d[i] = s[i];
        } else {
            float4 zz = make_float4(0.f,0.f,0.f,0.f);
            float4* d = (float4*)(Z + Hn*Bn);
            for (int i = tid; i < 2048; i += NTHR) d[i] = zz;
        }
        __syncthreads();

        // ---- gate GEMM microtile ----
        float a00,a01,a02,a03, a10,a11,a12,a13;
        if (layer == 0){
            int tb = t*Bn + b0;
            int tk0 = g_xT[tb+0], tk1 = g_xT[tb+1], tk2 = g_xT[tb+2], tk3 = g_xT[tb+3];
            a00 = g_tok[tk0*G4+gc0]; a01 = g_tok[tk1*G4+gc0];
            a02 = g_tok[tk2*G4+gc0]; a03 = g_tok[tk3*G4+gc0];
            a10 = g_tok[tk0*G4+gc1]; a11 = g_tok[tk1*G4+gc1];
            a12 = g_tok[tk2*G4+gc1]; a13 = g_tok[tk3*G4+gc1];
        } else {
            float bb0 = Bsm[c0], bb1 = Bsm[c0+1];
            a00=bb0; a01=bb0; a02=bb0; a03=bb0;
            a10=bb1; a11=bb1; a12=bb1; a13=bb1;
        }

        const int kstart = (layer == 0) ? Hn : 0;
#pragma unroll 8
        for (int k = kstart; k < 256; ++k){
            float4 zb = *(const float4*)&Z[k*Bn + b0];
            float2 w  = *(const float2*)&Wsm[k*NC + c0];
            a00 += w.x*zb.x; a01 += w.x*zb.y; a02 += w.x*zb.z; a03 += w.x*zb.w;
            a10 += w.y*zb.x; a11 += w.y*zb.y; a12 += w.y*zb.z; a13 += w.y*zb.w;
        }

        *(float4*)&Gsm[ c0   *Bn + b0] = make_float4(a00,a01,a02,a03);
        *(float4*)&Gsm[(c0+1)*Bn + b0] = make_float4(a10,a11,a12,a13);
        __syncthreads();

        // ---- elementwise LSTM cell (2 pairs per thread) ----
        float gi0 = Gsm[( 0+e_ul)*Bn + e_b    ];
        float gf0 = Gsm[( 8+e_ul)*Bn + e_b    ];
        float gg0 = Gsm[(16+e_ul)*Bn + e_b    ];
        float go0 = Gsm[(24+e_ul)*Bn + e_b    ];
        float gi1 = Gsm[( 0+e_ul)*Bn + e_b + 1];
        float gf1 = Gsm[( 8+e_ul)*Bn + e_b + 1];
        float gg1 = Gsm[(16+e_ul)*Bn + e_b + 1];
        float go1 = Gsm[(24+e_ul)*Bn + e_b + 1];

        float i0 = sigm(gi0), f0 = sigm(gf0), o0 = sigm(go0), g0 = tanhf(gg0);
        float i1 = sigm(gi1), f1 = sigm(gf1), o1 = sigm(go1), g1 = tanhf(gg1);
        cst0 = f0*cst0 + i0*g0;
        cst1 = f1*cst1 + i1*g1;
        float h0 = o0 * tanhf(cst0);
        float h1 = o1 * tanhf(cst1);

        *(float2*)&g_hseq[(layer*Tn + t)*Hn*Bn + e_u*Bn + e_b] = make_float2(h0, h1);

        if (t == Tn-1){
            out[OUT_H_BASE + (layer*Bn + e_b    )*Hn + e_u] = h0;
            out[OUT_H_BASE + (layer*Bn + e_b + 1)*Hn + e_u] = h1;
            out[OUT_C_BASE + (layer*Bn + e_b    )*Hn + e_u] = cst0;
            out[OUT_C_BASE + (layer*Bn + e_b + 1)*Hn + e_u] = cst1;
        }
        __syncthreads();   // all stores done (and Z/Gsm safe for reuse)
        if (tid == 0) red_rel_add(&cnt_own[t]);
    }
}

// ---------------------------------------------------------------------------
// Output projection: outputs[b][t][o] = h7[t][:,b] . w_out[:,o] + b_out[o]
__global__ void k_out(const float* __restrict__ w_out, const float* __restrict__ b_out,
                      float* __restrict__ out){
    extern __shared__ float sm[];
    float* Hs = sm;            // [128][64]
    float* Ws = sm + 8192;     // [128][65]
    int t = blockIdx.x, tid = threadIdx.x;

    const float4* s = (const float4*)&g_hseq[(7*Tn + t)*Hn*Bn];
    for (int i = tid; i < 2048; i += 256) ((float4*)Hs)[i] = s[i];
    for (int i = tid; i < Hn*On; i += 256) Ws[i] = w_out[i];
    __syncthreads();

    int b = tid & 63, og = tid >> 6;
    for (int o = og; o < On; o += 4){
        float acc = b_out[o];
#pragma unroll 8
        for (int k = 0; k < Hn; ++k) acc += Hs[k*Bn + b] * Ws[k*On + o];
        out[(b*Tn + t)*On + o] = acc;
    }
}

// ---------------------------------------------------------------------------
extern "C" void kernel_launch(void* const* d_in, const int* in_sizes, int n_in,
                              void* d_out, int out_size)
{
    const int*   x     = (const int*)  d_in[0];
    const float* embed = (const float*)d_in[1];
    const float* w_ih  = (const float*)d_in[2];
    const float* b_ih  = (const float*)d_in[3];
    const float* w_hh  = (const float*)d_in[4];
    const float* b_hh  = (const float*)d_in[5];
    const float* w_out = (const float*)d_in[6];
    const float* b_out = (const float*)d_in[7];
    float* out = (float*)d_out;

    size_t smem_lstm = (size_t)(8192 + 16384 + 2048 + 32) * sizeof(float);   // 106,624 B
    size_t smem_out  = (size_t)(8192 + Hn*On) * sizeof(float);               //  66,048 B
    cudaFuncSetAttribute(k_lstm, cudaFuncAttributeMaxDynamicSharedMemorySize, (int)smem_lstm);
    cudaFuncSetAttribute(k_out,  cudaFuncAttributeMaxDynamicSharedMemorySize, (int)smem_out);

    k_reset<<<128, 256>>>(x);
    k_token<<<Vn, G4>>>(embed, w_ih, b_ih, b_hh);
    k_lstm<<<Ln*CPL, NTHR, smem_lstm>>>(w_ih, b_ih, w_hh, b_hh, out);
    k_out<<<Tn, 256, smem_out>>>(w_out, b_out, out);
}